// round 15
// baseline (speedup 1.0000x reference)
#include <cuda_runtime.h>

// SSKernelDiag: out[h,l] = 2 * Re( sum_n Cc[h,n] * A[h,n]^l )
//   A = exp(abslog + i*phase), dtA = abslog + i*phase, Cc = C*(A-1)/dtA
// H=256, N=64, L=4096, CH=1.
//
// R15: q fully register-resident. Thread (lane=t, warp) loads qr[64] =
// conj A_rank^lane ONCE; main loop streams only W via smem broadcast:
// per 4-rank chunk 2 LDS.128 + 4 FFMA2, early-break at tile count.
// Decay truncation + rank sort (desc l_cut) -> per-tile rank-prefix.
// 128 threads, PARTS=2 (grid 512), ~160 regs -> 3 blocks/SM.

#define HH 256
#define NN 64
#define LL 4096
#define TILE 32
#define PARTS 2
#define JT 64              // tiles per block
#define NTHREADS 128
#define NWARPS 4
#define KPW 16             // tiles per warp
#define CUT 23.0f          // e^-23 ~ 1e-10 magnitude cutoff

typedef unsigned long long ull;

__device__ __forceinline__ float2 cmul(float2 a, float2 b) {
    return make_float2(fmaf(a.x, b.x, -(a.y * b.y)),
                       fmaf(a.x, b.y,  (a.y * b.x)));
}
__device__ __forceinline__ ull pack2(float x, float y) {
    ull r;
    asm("mov.b64 %0, {%1, %2};" : "=l"(r) : "f"(x), "f"(y));
    return r;
}
__device__ __forceinline__ float2 unpack2(ull v) {
    float x, y;
    asm("mov.b64 {%0, %1}, %2;" : "=f"(x), "=f"(y) : "l"(v));
    return make_float2(x, y);
}
__device__ __forceinline__ void ffma2(ull& acc, ull a, ull b) {
    asm("fma.rn.f32x2 %0, %1, %2, %0;" : "+l"(acc) : "l"(a), "l"(b));
}
__device__ __forceinline__ ull fadd2(ull a, ull b) {
    ull r;
    asm("add.rn.f32x2 %0, %1, %2;" : "=l"(r) : "l"(a), "l"(b));
    return r;
}

__global__ void __launch_bounds__(NTHREADS)
ssk_diag_kernel(const float* __restrict__ abslog,
                const float* __restrict__ phase,
                const float* __restrict__ C,
                float* __restrict__ out) {
    __shared__ float2 AR[NN];               // rank-indexed A
    __shared__ float2 CcR[NN];              // rank-indexed 2*Cc
    __shared__ float2 pw[NN][7];            // A^{8,16,24,32,64,128,256}
    __shared__ int    lcut[NN];
    __shared__ int    scnt[JT];
    __shared__ float2 sQr[NN][TILE];        // 16 KB: conj-packed A^t, rank idx
    __shared__ float2 sWbuf[NWARPS][NN];    // 2 KB: per-warp W staging

    const int bid  = blockIdx.x;
    const int h    = bid >> 1;
    const int part = bid & 1;
    const int tid  = threadIdx.x;
    const int warp = tid >> 5;
    const int lane = tid & 31;

    // ---- phase 1 (tid<64): params, A = exp(dtA), lcut ----
    float al = 0.f, ph = 0.f;
    float2 Av  = make_float2(0.f, 0.f);
    float2 Cin = make_float2(0.f, 0.f);
    if (tid < NN) {
        al  = abslog[h * NN + tid];
        ph  = phase[h * NN + tid];
        Cin = reinterpret_cast<const float2*>(C)[h * NN + tid];
        float er = __expf(al);
        float s0, c0;
        __sincosf(ph, &s0, &c0);
        Av = make_float2(er * c0, er * s0);
        lcut[tid] = (int)fminf((float)LL, CUT / (-al) + 1.0f);
    }
    __syncthreads();

    // ---- phase 2: rank + Cc + power table (0..63) | tile counts (64..127)
    if (tid < NN) {
        const int my = lcut[tid];
        int rank = 0;
        #pragma unroll 8
        for (int m = 0; m < NN; m++) {
            const int o = lcut[m];
            rank += (o > my) || (o == my && m < tid);
        }
        float2 Am1 = make_float2(Av.x - 1.0f, Av.y);
        float2 num = cmul(Cin, Am1);
        float  inv = 1.0f / fmaf(al, al, ph * ph);
        AR[rank]  = Av;
        CcR[rank] = make_float2(2.0f * (num.x * al + num.y * ph) * inv,
                                2.0f * (num.y * al - num.x * ph) * inv);
        float2 A2   = cmul(Av, Av);
        float2 A4   = cmul(A2, A2);
        float2 A8   = cmul(A4, A4);
        float2 A16  = cmul(A8, A8);
        float2 A24  = cmul(A16, A8);
        float2 A32  = cmul(A16, A16);
        float2 A64  = cmul(A32, A32);
        float2 A128 = cmul(A64, A64);
        float2 A256 = cmul(A128, A128);
        pw[rank][0] = A8;   pw[rank][1] = A16;  pw[rank][2] = A24;
        pw[rank][3] = A32;  pw[rank][4] = A64;  pw[rank][5] = A128;
        pw[rank][6] = A256;
    } else {
        const int j = tid - NN;                // [0,64)
        const int lmin = TILE * (part + PARTS * j);
        int c = 0;
        #pragma unroll 8
        for (int m = 0; m < NN; m++) c += (lcut[m] > lmin);
        scnt[j] = (c + 3) & ~3;
    }
    __syncthreads();

    // ---- phase 3a: sQr[r][t] = conj-packed A^t ; thread = (r, half) ----
    {
        const int r    = tid & 63;
        const int half = tid >> 6;             // [0,2): t in [16h, 16h+16)
        float2 A1 = AR[r];
        float2 P0 = half ? pw[r][1] : make_float2(1.0f, 0.0f);  // A^(16h)
        float2 P1 = half ? pw[r][2] : pw[r][0];                 // A^(16h+8)
        #pragma unroll
        for (int j = 0; j < 8; j++) {
            sQr[r][16 * half + j]     = make_float2(P0.x, -P0.y);
            sQr[r][16 * half + 8 + j] = make_float2(P1.x, -P1.y);
            P0 = cmul(P0, A1);
            P1 = cmul(P1, A1);
        }
    }
    // ---- phase 3b: W state per lane (ranks lane, lane+32) ----
    // first tile idx32 = part + 2*warp in [0,7]: bits over A^{32,64,128};
    // tile step per k is 8 tiles -> S = A^256.
    float2 W0, W1, S0, S1;
    {
        const int idx = part + PARTS * warp;
        float2 E0 = make_float2(1.0f, 0.0f);
        float2 E1 = make_float2(1.0f, 0.0f);
        #pragma unroll
        for (int b = 0; b < 3; b++) {
            if ((idx >> b) & 1) {
                E0 = cmul(E0, pw[lane][3 + b]);
                E1 = cmul(E1, pw[lane + 32][3 + b]);
            }
        }
        W0 = cmul(CcR[lane],      E0);
        W1 = cmul(CcR[lane + 32], E1);
        S0 = pw[lane][6];
        S1 = pw[lane + 32][6];
    }
    __syncthreads();

    // ---- load this thread's FULL q column into registers (one time) ----
    ull qr[NN];
    #pragma unroll
    for (int i = 0; i < NN; i++)
        qr[i] = *reinterpret_cast<const ull*>(&sQr[i][lane]);

    // ---- main: 16 tiles per warp; j = warp + 4k, tl = part + 2j ----
    float* outh = out + h * LL;
    const ulonglong2* wb = reinterpret_cast<const ulonglong2*>(sWbuf[warp]);

    #pragma unroll
    for (int k = 0; k < KPW; k++) {
        const int j  = warp + NWARPS * k;
        const int tl = part + PARTS * j;
        __syncwarp();
        sWbuf[warp][lane]      = W0;
        sWbuf[warp][lane + 32] = W1;
        __syncwarp();

        const int m = scnt[j];
        ull acc0 = pack2(0.0f, 0.0f);
        ull acc1 = acc0;
        #pragma unroll
        for (int r = 0; r < NN; r += 4) {
            if (r >= m) break;                 // warp-uniform
            ulonglong2 wa = wb[(r >> 1)];
            ulonglong2 wc = wb[(r >> 1) + 1];
            ffma2(acc0, wa.x, qr[r + 0]);
            ffma2(acc1, wa.y, qr[r + 1]);
            ffma2(acc0, wc.x, qr[r + 2]);
            ffma2(acc1, wc.y, qr[r + 3]);
        }
        float2 u = unpack2(fadd2(acc0, acc1));
        outh[TILE * tl + lane] = u.x + u.y;

        W0 = cmul(W0, S0);
        W1 = cmul(W1, S1);
    }
}

extern "C" void kernel_launch(void* const* d_in, const int* in_sizes, int n_in,
                              void* d_out, int out_size) {
    const float* abslog = (const float*)d_in[0];  // (H, N) f32
    const float* phase  = (const float*)d_in[1];  // (H, N) f32
    const float* C      = (const float*)d_in[2];  // (1, H, N, 2) f32
    float* out = (float*)d_out;                   // (1, H, L) f32

    ssk_diag_kernel<<<HH * PARTS, NTHREADS>>>(abslog, phase, C, out);
}

// round 16
// speedup vs baseline: 1.2886x; 1.2886x over previous
#include <cuda_runtime.h>

// SSKernelDiag: out[h,l] = 2 * Re( sum_n Cc[h,n] * A[h,n]^l )
//   A = exp(abslog + i*phase), dtA = abslog + i*phase, Cc = C*(A-1)/dtA
// H=256, N=64, L=4096, CH=1.
//
// R16: one block per head (prologue once, single launch), 512 threads /
// 16 warps so heavy heads keep 16-warp parallelism (8 tiles/warp).
// Decay truncation + rank sort (desc l_cut) -> per-tile active rank prefix.
// Transcendental-minimal prologue (sincos/exp only in phase 1; all other
// powers via 9-cmul binary table). Main: stage W (2 STS.64), then per
// 4-rank chunk 2 LDS.128 + 4 FFMA2; first chunk's q register-cached.

#define HH 256
#define NN 64
#define LL 4096
#define TILE 32
#define NTILES 128
#define NTHREADS 512
#define NWARPS 16
#define KPW 8              // tiles per warp
#define CUT 23.0f          // e^-23 ~ 1e-10 magnitude cutoff

typedef unsigned long long ull;

__device__ __forceinline__ float2 cmul(float2 a, float2 b) {
    return make_float2(fmaf(a.x, b.x, -(a.y * b.y)),
                       fmaf(a.x, b.y,  (a.y * b.x)));
}
__device__ __forceinline__ ull pack2(float x, float y) {
    ull r;
    asm("mov.b64 %0, {%1, %2};" : "=l"(r) : "f"(x), "f"(y));
    return r;
}
__device__ __forceinline__ float2 unpack2(ull v) {
    float x, y;
    asm("mov.b64 {%0, %1}, %2;" : "=f"(x), "=f"(y) : "l"(v));
    return make_float2(x, y);
}
__device__ __forceinline__ void ffma2(ull& acc, ull a, ull b) {
    asm("fma.rn.f32x2 %0, %1, %2, %0;" : "+l"(acc) : "l"(a), "l"(b));
}
__device__ __forceinline__ ull fadd2(ull a, ull b) {
    ull r;
    asm("add.rn.f32x2 %0, %1, %2;" : "=l"(r) : "l"(a), "l"(b));
    return r;
}

__global__ void __launch_bounds__(NTHREADS)
ssk_diag_kernel(const float* __restrict__ abslog,
                const float* __restrict__ phase,
                const float* __restrict__ C,
                float* __restrict__ out) {
    __shared__ float2 AR[NN];               // rank-indexed A
    __shared__ float2 CcR[NN];              // rank-indexed 2*Cc
    __shared__ float2 pw[NN][8];            // A^{4,8,16,32,64,128,256,512}
    __shared__ int    lcut[NN];
    __shared__ int    scnt[NTILES];
    __shared__ float2 sQr[NN][TILE];        // 16 KB: conj-packed A^t, rank idx
    __shared__ float2 sWbuf[NWARPS][NN];    // 8 KB: per-warp W staging

    const int h    = blockIdx.x;
    const int tid  = threadIdx.x;
    const int warp = tid >> 5;
    const int lane = tid & 31;

    // ---- phase 1 (tid<64): params, A = exp(dtA), lcut ----
    float al = 0.f, ph = 0.f;
    float2 Av  = make_float2(0.f, 0.f);
    float2 Cin = make_float2(0.f, 0.f);
    if (tid < NN) {
        al  = abslog[h * NN + tid];
        ph  = phase[h * NN + tid];
        Cin = reinterpret_cast<const float2*>(C)[h * NN + tid];
        float er = __expf(al);
        float s0, c0;
        __sincosf(ph, &s0, &c0);
        Av = make_float2(er * c0, er * s0);
        lcut[tid] = (int)fminf((float)LL, CUT / (-al) + 1.0f);
    }
    __syncthreads();

    // ---- phase 2: rank + Cc + power table (0..63) | counts (64..191) ----
    if (tid < NN) {
        const int my = lcut[tid];
        int rank = 0;
        #pragma unroll 8
        for (int m = 0; m < NN; m++) {
            const int o = lcut[m];
            rank += (o > my) || (o == my && m < tid);
        }
        float2 Am1 = make_float2(Av.x - 1.0f, Av.y);
        float2 num = cmul(Cin, Am1);
        float  inv = 1.0f / fmaf(al, al, ph * ph);
        AR[rank]  = Av;
        CcR[rank] = make_float2(2.0f * (num.x * al + num.y * ph) * inv,
                                2.0f * (num.y * al - num.x * ph) * inv);
        float2 A2   = cmul(Av, Av);
        float2 A4   = cmul(A2, A2);
        float2 A8   = cmul(A4, A4);
        float2 A16  = cmul(A8, A8);
        float2 A32  = cmul(A16, A16);
        float2 A64  = cmul(A32, A32);
        float2 A128 = cmul(A64, A64);
        float2 A256 = cmul(A128, A128);
        float2 A512 = cmul(A256, A256);
        pw[rank][0] = A4;   pw[rank][1] = A8;   pw[rank][2] = A16;
        pw[rank][3] = A32;  pw[rank][4] = A64;  pw[rank][5] = A128;
        pw[rank][6] = A256; pw[rank][7] = A512;
    } else if (tid < NN + NTILES) {
        const int j = tid - NN;                 // tile in [0,128)
        const int lmin = TILE * j;
        int c = 0;
        #pragma unroll 8
        for (int m = 0; m < NN; m++) c += (lcut[m] > lmin);
        scnt[j] = (c + 3) & ~3;
    }
    __syncthreads();

    // ---- phase 3a: sQr[r][t] = conj-packed A^t ; thread = (r, q8) ----
    {
        const int r  = tid & 63;
        const int q8 = tid >> 6;                // [0,8): t in [4q8, 4q8+4)
        float2 A1 = AR[r];
        float2 P  = make_float2(1.0f, 0.0f);    // A^(4*q8) from bits of q8
        #pragma unroll
        for (int b = 0; b < 3; b++)
            if ((q8 >> b) & 1) P = cmul(P, pw[r][b]);
        #pragma unroll
        for (int j = 0; j < 4; j++) {
            sQr[r][4 * q8 + j] = make_float2(P.x, -P.y);
            P = cmul(P, A1);
        }
    }
    // ---- phase 3b: W state per lane (ranks lane, lane+32) ----
    // first tile = warp in [0,16): anchor A^(32*warp), bits over A^{32..256};
    // tile stride 16 -> step A^512.
    float2 W0, W1, S0, S1;
    {
        float2 E0 = make_float2(1.0f, 0.0f);
        float2 E1 = make_float2(1.0f, 0.0f);
        #pragma unroll
        for (int b = 0; b < 4; b++) {
            if ((warp >> b) & 1) {
                E0 = cmul(E0, pw[lane][3 + b]);
                E1 = cmul(E1, pw[lane + 32][3 + b]);
            }
        }
        W0 = cmul(CcR[lane],      E0);
        W1 = cmul(CcR[lane + 32], E1);
        S0 = pw[lane][7];
        S1 = pw[lane + 32][7];
    }
    __syncthreads();

    // ---- register-cache first chunk's q (ranks 0..3) ----
    ull qr0 = *reinterpret_cast<const ull*>(&sQr[0][lane]);
    ull qr1 = *reinterpret_cast<const ull*>(&sQr[1][lane]);
    ull qr2 = *reinterpret_cast<const ull*>(&sQr[2][lane]);
    ull qr3 = *reinterpret_cast<const ull*>(&sQr[3][lane]);

    // ---- main: 8 tiles per warp; tl = warp + 16k ----
    float* outh = out + h * LL;
    const ulonglong2* wb = reinterpret_cast<const ulonglong2*>(sWbuf[warp]);

    #pragma unroll
    for (int k = 0; k < KPW; k++) {
        const int tl = warp + NWARPS * k;
        __syncwarp();
        sWbuf[warp][lane]      = W0;
        sWbuf[warp][lane + 32] = W1;
        __syncwarp();

        const int m = scnt[tl];
        ull acc0 = pack2(0.0f, 0.0f);
        ull acc1 = acc0;
        if (m > 0) {
            ulonglong2 wa = wb[0], wc = wb[1];
            ffma2(acc0, wa.x, qr0);
            ffma2(acc1, wa.y, qr1);
            ffma2(acc0, wc.x, qr2);
            ffma2(acc1, wc.y, qr3);
            for (int r = 4; r < m; r += 4) {
                ulonglong2 w0 = wb[(r >> 1)];
                ulonglong2 w1 = wb[(r >> 1) + 1];
                ull q0 = *reinterpret_cast<const ull*>(&sQr[r + 0][lane]);
                ull q1 = *reinterpret_cast<const ull*>(&sQr[r + 1][lane]);
                ull q2 = *reinterpret_cast<const ull*>(&sQr[r + 2][lane]);
                ull q3 = *reinterpret_cast<const ull*>(&sQr[r + 3][lane]);
                ffma2(acc0, w0.x, q0);
                ffma2(acc1, w0.y, q1);
                ffma2(acc0, w1.x, q2);
                ffma2(acc1, w1.y, q3);
            }
        }
        float2 u = unpack2(fadd2(acc0, acc1));
        outh[TILE * tl + lane] = u.x + u.y;

        W0 = cmul(W0, S0);
        W1 = cmul(W1, S1);
    }
}

extern "C" void kernel_launch(void* const* d_in, const int* in_sizes, int n_in,
                              void* d_out, int out_size) {
    const float* abslog = (const float*)d_in[0];  // (H, N) f32
    const float* phase  = (const float*)d_in[1];  // (H, N) f32
    const float* C      = (const float*)d_in[2];  // (1, H, N, 2) f32
    float* out = (float*)d_out;                   // (1, H, L) f32

    ssk_diag_kernel<<<HH, NTHREADS>>>(abslog, phase, C, out);
}

// round 17
// speedup vs baseline: 1.7041x; 1.3225x over previous
#include <cuda_runtime.h>

// SSKernelDiag: out[h,l] = 2 * Re( sum_n Cc[h,n] * A[h,n]^l )
//   A = exp(abslog + i*phase), dtA = abslog + i*phase, Cc = C*(A-1)/dtA
// H=256, N=64, L=4096, CH=1.
//
// R17: q amortized over tile QUADS. One block per head (prologue once),
// 256 threads / 8 warps; warp owns quads j = warp + 8k (k<4), quad j =
// tiles {4j..4j+3}. Per quad: stage W_d = W * A^{32d} (d<4) for all 64
// ranks into smem; inner loop per 4-rank chunk: 4 LDS.64 (q, ONCE for all
// 4 tiles) + 8 broadcast LDS.128 (W) + 16 FFMA2 on 4 accumulators.
// Decay truncation + rank sort (desc l_cut) -> per-quad active rank prefix.
// Transcendental-minimal prologue (sincos/exp only once per n).

#define HH 256
#define NN 64
#define LL 4096
#define TILE 32
#define NQUADS 32
#define NTHREADS 256
#define NWARPS 8
#define KPW 4              // quads per warp
#define CUT 23.0f          // e^-23 ~ 1e-10 magnitude cutoff

typedef unsigned long long ull;

__device__ __forceinline__ float2 cmul(float2 a, float2 b) {
    return make_float2(fmaf(a.x, b.x, -(a.y * b.y)),
                       fmaf(a.x, b.y,  (a.y * b.x)));
}
__device__ __forceinline__ ull pack2(float x, float y) {
    ull r;
    asm("mov.b64 %0, {%1, %2};" : "=l"(r) : "f"(x), "f"(y));
    return r;
}
__device__ __forceinline__ float2 unpack2(ull v) {
    float x, y;
    asm("mov.b64 {%0, %1}, %2;" : "=f"(x), "=f"(y) : "l"(v));
    return make_float2(x, y);
}
__device__ __forceinline__ void ffma2(ull& acc, ull a, ull b) {
    asm("fma.rn.f32x2 %0, %1, %2, %0;" : "+l"(acc) : "l"(a), "l"(b));
}

__global__ void __launch_bounds__(NTHREADS)
ssk_diag_kernel(const float* __restrict__ abslog,
                const float* __restrict__ phase,
                const float* __restrict__ C,
                float* __restrict__ out) {
    __shared__ float2 AR[NN];                  // rank-indexed A
    __shared__ float2 CcR[NN];                 // rank-indexed 2*Cc
    __shared__ float2 pw[NN][9];               // A^{8,16,32,64,96,128,256,512,1024}
    __shared__ int    lcut[NN];
    __shared__ int    scnt[NQUADS];            // active ranks per quad (ceil 4)
    __shared__ float2 sQr[NN][TILE];           // 16 KB: conj-packed A^t
    __shared__ float2 sWbuf[NWARPS][4][NN];    // 16 KB: per-warp W x 4 tiles

    const int h    = blockIdx.x;
    const int tid  = threadIdx.x;
    const int warp = tid >> 5;
    const int lane = tid & 31;

    const float* alh = abslog + h * NN;
    const float* phh = phase  + h * NN;

    // ---- phase 1 (tid<64): params, A = exp(dtA), lcut ----
    float al = 0.f, ph = 0.f;
    float2 Av  = make_float2(0.f, 0.f);
    float2 Cin = make_float2(0.f, 0.f);
    if (tid < NN) {
        al  = alh[tid];
        ph  = phh[tid];
        Cin = reinterpret_cast<const float2*>(C)[h * NN + tid];
        float er = __expf(al);
        float s0, c0;
        __sincosf(ph, &s0, &c0);
        Av = make_float2(er * c0, er * s0);
        lcut[tid] = (int)fminf((float)LL, CUT / (-al) + 1.0f);
    }
    __syncthreads();

    // ---- phase 2: rank + Cc + power table (0..63) | quad counts (64..95) ----
    if (tid < NN) {
        const int my = lcut[tid];
        int rank = 0;
        #pragma unroll 8
        for (int m = 0; m < NN; m++) {
            const int o = lcut[m];
            rank += (o > my) || (o == my && m < tid);
        }
        float2 Am1 = make_float2(Av.x - 1.0f, Av.y);
        float2 num = cmul(Cin, Am1);
        float  inv = 1.0f / fmaf(al, al, ph * ph);
        AR[rank]  = Av;
        CcR[rank] = make_float2(2.0f * (num.x * al + num.y * ph) * inv,
                                2.0f * (num.y * al - num.x * ph) * inv);
        float2 A2    = cmul(Av, Av);
        float2 A4    = cmul(A2, A2);
        float2 A8    = cmul(A4, A4);
        float2 A16   = cmul(A8, A8);
        float2 A32   = cmul(A16, A16);
        float2 A64   = cmul(A32, A32);
        float2 A96   = cmul(A64, A32);
        float2 A128  = cmul(A64, A64);
        float2 A256  = cmul(A128, A128);
        float2 A512  = cmul(A256, A256);
        float2 A1024 = cmul(A512, A512);
        pw[rank][0] = A8;    pw[rank][1] = A16;  pw[rank][2] = A32;
        pw[rank][3] = A64;   pw[rank][4] = A96;  pw[rank][5] = A128;
        pw[rank][6] = A256;  pw[rank][7] = A512; pw[rank][8] = A1024;
    } else if (tid < NN + NQUADS) {
        const int j = tid - NN;                 // quad in [0,32)
        const int lmin = 128 * j;               // first l of tile 4j
        int c = 0;
        #pragma unroll 8
        for (int m = 0; m < NN; m++) c += (lcut[m] > lmin);
        scnt[j] = (c + 3) & ~3;
    }
    __syncthreads();

    // ---- phase 3a: sQr[r][t] = conj-packed A^t ; thread = (r, q4) ----
    {
        const int r  = tid & 63;
        const int q4 = tid >> 6;                // [0,4): t in [8q4, 8q4+8)
        float2 A1 = AR[r];
        float2 P  = make_float2(1.0f, 0.0f);    // A^(8*q4)
        if (q4 & 1) P = pw[r][0];
        if (q4 & 2) P = cmul(P, pw[r][1]);
        #pragma unroll
        for (int j = 0; j < 8; j++) {
            sQr[r][8 * q4 + j] = make_float2(P.x, -P.y);
            P = cmul(P, A1);
        }
    }
    // ---- phase 3b: W state per lane (ranks lane, lane+32) ----
    // first quad = warp: anchor A^(128*warp), bits over A^{128,256,512};
    // quad stride 8 -> step A^1024.
    float2 W0, W1, S0, S1;
    {
        float2 E0 = make_float2(1.0f, 0.0f);
        float2 E1 = make_float2(1.0f, 0.0f);
        #pragma unroll
        for (int b = 0; b < 3; b++) {
            if ((warp >> b) & 1) {
                E0 = cmul(E0, pw[lane][5 + b]);
                E1 = cmul(E1, pw[lane + 32][5 + b]);
            }
        }
        W0 = cmul(CcR[lane],      E0);
        W1 = cmul(CcR[lane + 32], E1);
        S0 = pw[lane][8];
        S1 = pw[lane + 32][8];
    }
    __syncthreads();

    // ---- main: 4 quads per warp; quad j = warp + 8k, tiles {4j..4j+3} ----
    float* outh = out + h * LL;
    const ulonglong2* wb0 = reinterpret_cast<const ulonglong2*>(sWbuf[warp][0]);
    const ulonglong2* wb1 = reinterpret_cast<const ulonglong2*>(sWbuf[warp][1]);
    const ulonglong2* wb2 = reinterpret_cast<const ulonglong2*>(sWbuf[warp][2]);
    const ulonglong2* wb3 = reinterpret_cast<const ulonglong2*>(sWbuf[warp][3]);

    #pragma unroll
    for (int k = 0; k < KPW; k++) {
        const int j = warp + NWARPS * k;

        // stage W for 4 tiles x 2 ranks (this lane's ranks)
        __syncwarp();
        {
            float2 a32_0 = pw[lane][2],      a64_0 = pw[lane][3],      a96_0 = pw[lane][4];
            float2 a32_1 = pw[lane + 32][2], a64_1 = pw[lane + 32][3], a96_1 = pw[lane + 32][4];
            sWbuf[warp][0][lane]      = W0;
            sWbuf[warp][0][lane + 32] = W1;
            sWbuf[warp][1][lane]      = cmul(W0, a32_0);
            sWbuf[warp][1][lane + 32] = cmul(W1, a32_1);
            sWbuf[warp][2][lane]      = cmul(W0, a64_0);
            sWbuf[warp][2][lane + 32] = cmul(W1, a64_1);
            sWbuf[warp][3][lane]      = cmul(W0, a96_0);
            sWbuf[warp][3][lane + 32] = cmul(W1, a96_1);
        }
        __syncwarp();

        const int m = scnt[j];
        ull acc0 = pack2(0.0f, 0.0f);
        ull acc1 = acc0, acc2 = acc0, acc3 = acc0;
        for (int r = 0; r < m; r += 4) {
            const int rr = r >> 1;
            ull q0 = *reinterpret_cast<const ull*>(&sQr[r + 0][lane]);
            ull q1 = *reinterpret_cast<const ull*>(&sQr[r + 1][lane]);
            ull q2 = *reinterpret_cast<const ull*>(&sQr[r + 2][lane]);
            ull q3 = *reinterpret_cast<const ull*>(&sQr[r + 3][lane]);
            ulonglong2 wa0 = wb0[rr], wc0 = wb0[rr + 1];
            ulonglong2 wa1 = wb1[rr], wc1 = wb1[rr + 1];
            ulonglong2 wa2 = wb2[rr], wc2 = wb2[rr + 1];
            ulonglong2 wa3 = wb3[rr], wc3 = wb3[rr + 1];
            ffma2(acc0, wa0.x, q0); ffma2(acc1, wa1.x, q0);
            ffma2(acc2, wa2.x, q0); ffma2(acc3, wa3.x, q0);
            ffma2(acc0, wa0.y, q1); ffma2(acc1, wa1.y, q1);
            ffma2(acc2, wa2.y, q1); ffma2(acc3, wa3.y, q1);
            ffma2(acc0, wc0.x, q2); ffma2(acc1, wc1.x, q2);
            ffma2(acc2, wc2.x, q2); ffma2(acc3, wc3.x, q2);
            ffma2(acc0, wc0.y, q3); ffma2(acc1, wc1.y, q3);
            ffma2(acc2, wc2.y, q3); ffma2(acc3, wc3.y, q3);
        }
        {
            float2 u0 = unpack2(acc0), u1 = unpack2(acc1);
            float2 u2 = unpack2(acc2), u3 = unpack2(acc3);
            float* o = outh + 128 * j + lane;
            o[0]  = u0.x + u0.y;
            o[32] = u1.x + u1.y;
            o[64] = u2.x + u2.y;
            o[96] = u3.x + u3.y;
        }
        W0 = cmul(W0, S0);
        W1 = cmul(W1, S1);
    }
}

extern "C" void kernel_launch(void* const* d_in, const int* in_sizes, int n_in,
                              void* d_out, int out_size) {
    const float* abslog = (const float*)d_in[0];  // (H, N) f32
    const float* phase  = (const float*)d_in[1];  // (H, N) f32
    const float* C      = (const float*)d_in[2];  // (1, H, N, 2) f32
    float* out = (float*)d_out;                   // (1, H, L) f32

    ssk_diag_kernel<<<HH, NTHREADS>>>(abslog, phase, C, out);
}